// round 5
// baseline (speedup 1.0000x reference)
#include <cuda_runtime.h>
#include <cstdint>

// Problem constants (from reference)
#define S_SCALE 64.0f
#define MARGIN  0.35f
#define BATCH   4096u
#define NUM_CLASSES 50257u

// One block per row. 4096 blocks x 256 threads; all blocks fit resident in a
// single wave (4096 < 148 SMs * 32 CTAs), perfectly balanced.
// Each thread broadcasts-loads the row's label once (L1 broadcast, no barrier,
// no smem), then streams ~49 float4 chunks with one range-compare each.
// Rows are 50257 floats, so row starts are only 4-aligned every 4th row:
// scalar head/tail around an aligned float4 body.
__global__ void __launch_bounds__(256) cosface_row_kernel(
    const float* __restrict__ in,
    const int*   __restrict__ labels,
    float*       __restrict__ out)
{
    const unsigned int r     = blockIdx.x;
    const unsigned int base  = r * NUM_CLASSES;      // max 205,802,415 < 2^31
    const unsigned int tid   = threadIdx.x;

    const int lab = __ldg(labels + r);               // warp/L1 broadcast
    const unsigned int labcol = (lab >= 0) ? (unsigned int)lab : 0xFFFFFFFFu;

    // Alignment: element offset 'head' such that (base + head) % 4 == 0.
    const unsigned int head = (4u - (base & 3u)) & 3u;   // 0..3 scalar elems

    // --- scalar head ---
    if (tid < head) {
        const unsigned int c = tid;
        float x = in[base + c];
        if (c == labcol) x -= MARGIN;
        out[base + c] = x * S_SCALE;
    }

    // --- aligned float4 body ---
    const unsigned int remaining = NUM_CLASSES - head;
    const unsigned int nvec      = remaining >> 2;       // float4 count
    const float4* __restrict__ in4  = (const float4*)(in  + base + head);
    float4*       __restrict__ out4 = (float4*)      (out + base + head);

    #pragma unroll 4
    for (unsigned int j = tid; j < nvec; j += 256u) {
        float4 v = in4[j];
        const unsigned int c = head + (j << 2);          // column of v.x
        const unsigned int d = labcol - c;               // in-range iff < 4
        if (d < 4u) {
            if (d == 0u) v.x -= MARGIN;
            if (d == 1u) v.y -= MARGIN;
            if (d == 2u) v.z -= MARGIN;
            if (d == 3u) v.w -= MARGIN;
        }
        v.x *= S_SCALE;
        v.y *= S_SCALE;
        v.z *= S_SCALE;
        v.w *= S_SCALE;
        out4[j] = v;
    }

    // --- scalar tail ---
    const unsigned int tail_start = head + (nvec << 2);
    const unsigned int c = tail_start + tid;
    if (c < NUM_CLASSES) {
        float x = in[base + c];
        if (c == labcol) x -= MARGIN;
        out[base + c] = x * S_SCALE;
    }
}

extern "C" void kernel_launch(void* const* d_in, const int* in_sizes, int n_in,
                              void* d_out, int out_size)
{
    const float* logits = (const float*)d_in[0];
    const int*   labels = (const int*)d_in[1];
    float*       out    = (float*)d_out;

    (void)in_sizes; (void)n_in; (void)out_size;

    cosface_row_kernel<<<BATCH, 256>>>(logits, labels, out);
}

// round 6
// speedup vs baseline: 1.0607x; 1.0607x over previous
#include <cuda_runtime.h>
#include <cstdint>

// Problem constants (from reference)
#define S_SCALE 64.0f
#define MARGIN  0.35f
#define BATCH   4096u
#define NUM_CLASSES 50257u

// Total elements = 4096 * 50257 = 205,852,672 ; divisible by 4 -> exact float4 tiling.
#define N_TOTAL 205852672u
#define N_VEC4  (N_TOTAL / 4u)   // 51,463,168 ; / 256 = 201,028 blocks exactly

// Fused streaming kernel with WARP-LEVEL label gating (no barrier, no smem).
// A warp covers 128 consecutive elements -> spans at most 2 rows.
// Lanes 0/1 load the two candidate labels; shfl broadcasts them; every thread
// then does two unsigned range-compares against its 4-element chunk.
__global__ void __launch_bounds__(256) cosface_warp_kernel(
    const float4* __restrict__ in,
    const int*    __restrict__ labels,
    float4*       __restrict__ out)
{
    const unsigned int i = blockIdx.x * 256u + threadIdx.x;   // grid is exact
    float4 v = in[i];                                          // issue main load first

    const unsigned int lane    = threadIdx.x & 31u;
    const unsigned int warp_e0 = (i & ~31u) * 4u;              // warp's first element
    const unsigned int r0 = warp_e0 / NUM_CLASSES;             // umulhi const-div
    const unsigned int r1 = (warp_e0 + 127u) / NUM_CLASSES;    // r0 or r0+1

    int lab = 0;
    if (lane < 2u) {
        lab = __ldg(labels + ((lane == 0u) ? r0 : r1));        // L1-hot broadcast
    }
    const int lab0 = __shfl_sync(0xFFFFFFFFu, lab, 0);
    const int lab1 = __shfl_sync(0xFFFFFFFFu, lab, 1);

    const unsigned int p0 = (lab0 >= 0) ? (r0 * NUM_CLASSES + (unsigned int)lab0)
                                        : 0xFFFFFFFFu;
    const unsigned int p1 = (lab1 >= 0) ? (r1 * NUM_CLASSES + (unsigned int)lab1)
                                        : 0xFFFFFFFFu;

    const unsigned int e  = i * 4u;
    const unsigned int d0 = p0 - e;   // unsigned wrap: in-range iff < 4
    const unsigned int d1 = p1 - e;

    if (d0 < 4u || d1 < 4u) {         // taken by <=2 threads per affected warp
        if (d0 == 0u || d1 == 0u) v.x -= MARGIN;
        if (d0 == 1u || d1 == 1u) v.y -= MARGIN;
        if (d0 == 2u || d1 == 2u) v.z -= MARGIN;
        if (d0 == 3u || d1 == 3u) v.w -= MARGIN;
    }

    v.x *= S_SCALE;
    v.y *= S_SCALE;
    v.z *= S_SCALE;
    v.w *= S_SCALE;
    out[i] = v;
}

extern "C" void kernel_launch(void* const* d_in, const int* in_sizes, int n_in,
                              void* d_out, int out_size)
{
    const float* logits = (const float*)d_in[0];
    const int*   labels = (const int*)d_in[1];
    float*       out    = (float*)d_out;

    (void)in_sizes; (void)n_in; (void)out_size;

    dim3 grid(N_VEC4 / 256u);   // 201,028 blocks, exact
    cosface_warp_kernel<<<grid, 256>>>((const float4*)logits, labels, (float4*)out);
}

// round 9
// speedup vs baseline: 1.0947x; 1.0321x over previous
#include <cuda_runtime.h>
#include <cstdint>

// Problem constants (from reference)
#define S_SCALE 64.0f
#define MARGIN  0.35f
#define BATCH   4096
#define NUM_CLASSES 50257u

// Total elements = 4096 * 50257 = 205,852,672 ; divisible by 4 -> exact float4 tiling.
#define N_TOTAL 205852672u
#define N_VEC4  (N_TOTAL / 4u)   // 51,463,168 ; / 256 = 201,028 blocks exactly

// Primary: pure streaming scale, float4, streaming cache hints.
// Triggers programmatic launch completion immediately so the fixup kernel can
// begin its (input-only) gather during our tail wave.
__global__ void __launch_bounds__(256) cosface_copy_kernel(
    const float4* __restrict__ in, float4* __restrict__ out)
{
    cudaTriggerProgrammaticLaunchCompletion();

    const unsigned int i = blockIdx.x * 256u + threadIdx.x;  // grid exact, no guard
    float4 v = __ldcs(in + i);
    v.x *= S_SCALE;
    v.y *= S_SCALE;
    v.z *= S_SCALE;
    v.w *= S_SCALE;
    __stcs(out + i, v);
}

// Secondary (PDL): per-row fixup. Gather phase runs overlapped with the
// primary (reads only primary's INPUTS); only the store waits on grid sync.
__global__ void __launch_bounds__(512) cosface_fixup_pdl_kernel(
    const float* __restrict__ logits,
    const int*   __restrict__ labels,
    float*       __restrict__ out)
{
    const int row = blockIdx.x * 512 + threadIdx.x;

    // Prelude: independent of primary's output — overlaps with primary.
    int lab = -1;
    size_t idx = 0;
    float val = 0.0f;
    if (row < BATCH) {
        lab = labels[row];
        if (lab >= 0 && lab < (int)NUM_CLASSES) {
            idx = (size_t)row * NUM_CLASSES + (size_t)lab;
            val = (__ldg(logits + idx) - MARGIN) * S_SCALE;
        }
    }

    // Wait for primary's stores to out, then overwrite the label positions.
    cudaGridDependencySynchronize();

    if (row < BATCH && lab >= 0 && lab < (int)NUM_CLASSES) {
        out[idx] = val;
    }
}

extern "C" void kernel_launch(void* const* d_in, const int* in_sizes, int n_in,
                              void* d_out, int out_size)
{
    const float* logits = (const float*)d_in[0];
    const int*   labels = (const int*)d_in[1];
    float*       out    = (float*)d_out;

    (void)in_sizes; (void)n_in; (void)out_size;

    // Primary streaming kernel.
    cosface_copy_kernel<<<N_VEC4 / 256u, 256>>>((const float4*)logits, (float4*)out);

    // Secondary with programmatic stream serialization (PDL edge, graph-capturable).
    cudaLaunchConfig_t cfg = {};
    cfg.gridDim  = dim3((BATCH + 511) / 512);   // 8 blocks
    cfg.blockDim = dim3(512);
    cfg.dynamicSmemBytes = 0;
    cfg.stream = 0;

    cudaLaunchAttribute attr[1];
    attr[0].id = cudaLaunchAttributeProgrammaticStreamSerialization;
    attr[0].val.programmaticStreamSerializationAllowed = 1;
    cfg.attrs = attr;
    cfg.numAttrs = 1;

    cudaLaunchKernelEx(&cfg, cosface_fixup_pdl_kernel, logits, labels, out);
}